// round 11
// baseline (speedup 1.0000x reference)
#include <cuda_runtime.h>
#include <math.h>

#define BN_INV 0.9999950000374997f

typedef unsigned long long u64;

__device__ __forceinline__ u64 ffma2(u64 a, u64 b, u64 c) {
    u64 d;
    asm("fma.rn.f32x2 %0, %1, %2, %3;" : "=l"(d) : "l"(a), "l"(b), "l"(c));
    return d;
}
__device__ __forceinline__ u64 pack2(float lo, float hi) {
    u64 r;
    asm("mov.b64 %0, {%1, %2};" : "=l"(r) : "f"(lo), "f"(hi));
    return r;
}
__device__ __forceinline__ float2 unpack2(u64 v) {
    float2 f;
    asm("mov.b64 {%0, %1}, %2;" : "=f"(f.x), "=f"(f.y) : "l"(v));
    return f;
}

// Scratch (allocation-free rule -> __device__ globals)
__device__ float2 g_h1p[1024 * 4608];   // stage1 out, pair-interleaved
__device__ float2 g_h2p[1024 * 1024];   // stage2 out, pair-interleaved
__device__ float  g_w1q[1024 * 512];    // fc1 weights, [kq][oc][4] quad layout

// ---------------------------------------------------------------------------
// Paired block reduce (256 threads = 8 warps); sred must hold >= 16 floats
// ---------------------------------------------------------------------------
__device__ __forceinline__ float2 blockReduceSum2(float2 v, volatile float* sred, int tid) {
#pragma unroll
    for (int o = 16; o > 0; o >>= 1) {
        v.x += __shfl_xor_sync(0xffffffffu, v.x, o);
        v.y += __shfl_xor_sync(0xffffffffu, v.y, o);
    }
    if ((tid & 31) == 0) {
        sred[(tid >> 5) * 2]     = v.x;
        sred[(tid >> 5) * 2 + 1] = v.y;
    }
    __syncthreads();
    if (tid < 32) {
        float a = (tid < 8) ? sred[tid * 2] : 0.f;
        float b = (tid < 8) ? sred[tid * 2 + 1] : 0.f;
#pragma unroll
        for (int o = 4; o > 0; o >>= 1) {
            a += __shfl_xor_sync(0xffffffffu, a, o);
            b += __shfl_xor_sync(0xffffffffu, b, o);
        }
        if (tid == 0) { sred[0] = a; sred[1] = b; }
    }
    __syncthreads();
    float2 r = make_float2(sred[0], sred[1]);
    __syncthreads();
    return r;
}

// ---------------------------------------------------------------------------
// Kernel 0: repack fc1 weights  w1[512][1024] -> g_w1q[kq][oc][4]
// ---------------------------------------------------------------------------
__global__ __launch_bounds__(256) void k_tw1(const float* __restrict__ w1) {
    int idx = blockIdx.x * 256 + threadIdx.x;   // 131072 = 256 kq * 512 oc
    int kq = idx >> 9;
    int oc = idx & 511;
    float4 v = *(const float4*)(w1 + oc * 1024 + kq * 4);
    *(float4*)(g_w1q + kq * 2048 + oc * 4) = v;
}

// ---------------------------------------------------------------------------
// Kernel 1: conv1(1->32, 5x5, 28->24) + tern + BN + maxpool2 + relu
// 2 samples/CTA, f32x2, lane = oc / warp = oy remap. (unchanged)
// ---------------------------------------------------------------------------
__global__ __launch_bounds__(256) void k_conv1(
    const float* __restrict__ x, const float* __restrict__ w,
    const float* __restrict__ bconv, const float* __restrict__ bng,
    const float* __restrict__ bnb) {
    extern __shared__ float sm[];
    float2* s_in2   = (float2*)sm;            // 812 float2
    float*  s_w     = sm + 1624;              // 800
    float*  s_b     = sm + 2424;              // 32
    float2* s_conv2 = (float2*)(sm + 2456);   // 32 * 577 = 18464 float2
    __shared__ float sred[16];

    const int n2 = blockIdx.x;
    const int tid = threadIdx.x;

    const float* x0 = x + (2 * n2) * 784;
    const float* x1 = x + (2 * n2 + 1) * 784;
    for (int i = tid; i < 784; i += 256) {
        int r = i / 28, c = i - r * 28;
        s_in2[r * 29 + c] = make_float2(x0[i], x1[i]);
    }
    for (int i = tid; i < 800; i += 256) s_w[i] = w[i];
    if (tid < 32) s_b[tid] = bconv[tid];
    __syncthreads();

    const int oc  = tid & 31;
    const int wrp = tid >> 5;

    float2 labs = make_float2(0.f, 0.f);
#pragma unroll
    for (int p = 0; p < 3; p++) {
        int oy = p * 8 + wrp;
        u64 acc[24];
        {
            float b = s_b[oc];
            u64 bb = pack2(b, b);
#pragma unroll
            for (int ox = 0; ox < 24; ox++) acc[ox] = bb;
        }
#pragma unroll
        for (int kh = 0; kh < 5; kh++) {
            u64 row[28];
            const u64* rp = (const u64*)(s_in2 + (oy + kh) * 29);
#pragma unroll
            for (int j = 0; j < 28; j++) row[j] = rp[j];
            const float* wp = s_w + oc * 25 + kh * 5;
#pragma unroll
            for (int kw = 0; kw < 5; kw++) {
                float s = wp[kw];
                u64 wd = pack2(s, s);
#pragma unroll
                for (int ox = 0; ox < 24; ox++)
                    acc[ox] = ffma2(wd, row[ox + kw], acc[ox]);
            }
        }
        float2* cp = s_conv2 + oc * 577 + oy * 24;
#pragma unroll
        for (int ox = 0; ox < 24; ox++) {
            float2 v = unpack2(acc[ox]);
            cp[ox] = v;
            labs.x += fabsf(v.x);
            labs.y += fabsf(v.y);
        }
    }

    float2 tot = blockReduceSum2(labs, sred, tid);
    float d0 = 0.7f * tot.x / 18432.0f;
    float d1 = 0.7f * tot.y / 18432.0f;

    float2 ms = make_float2(0.f, 0.f), cn = make_float2(0.f, 0.f);
    for (int i = tid; i < 18432; i += 256) {
        int c = i / 576, r = i - c * 576;
        float2 v = s_conv2[c * 577 + r];
        float a;
        a = fabsf(v.x); if (a > d0) { ms.x += a; cn.x += 1.f; }
        a = fabsf(v.y); if (a > d1) { ms.y += a; cn.y += 1.f; }
    }
    ms = blockReduceSum2(ms, sred, tid);
    cn = blockReduceSum2(cn, sred, tid);
    float a0v = ms.x / cn.x;
    float a1v = ms.y / cn.y;

    float2* outp = g_h1p + n2 * 4608;
    for (int p = tid; p < 4608; p += 256) {
        int c = p / 144;
        int r = p - c * 144;
        int py = r / 12, px = r - py * 12;
        float sc = __ldg(bng + c) * BN_INV, sh = __ldg(bnb + c);
        const float2* base = s_conv2 + c * 577 + (py * 2) * 24 + px * 2;
        float m0 = -1e30f, m1 = -1e30f;
#pragma unroll
        for (int dy = 0; dy < 2; dy++)
#pragma unroll
            for (int dx = 0; dx < 2; dx++) {
                float2 v = base[dy * 24 + dx];
                float t0 = (v.x > d0) ? a0v : ((v.x < -d0) ? -a0v : 0.f);
                float t1 = (v.y > d1) ? a1v : ((v.y < -d1) ? -a1v : 0.f);
                m0 = fmaxf(m0, t0 * sc + sh);
                m1 = fmaxf(m1, t1 * sc + sh);
            }
        outp[p] = make_float2(fmaxf(m0, 0.f), fmaxf(m1, 0.f));
    }
}

// ---------------------------------------------------------------------------
// Kernel 2: conv2(32->64, 5x5, 12->8) + tern + BN + maxpool2 + relu
// 2 samples/CTA f32x2, staged weights, s_conv2 aliases s_in2. (unchanged)
// ---------------------------------------------------------------------------
__global__ __launch_bounds__(256) void k_conv2(
    const float* __restrict__ w, const float* __restrict__ bconv,
    const float* __restrict__ bng, const float* __restrict__ bnb) {
    extern __shared__ float smraw[];
    float2* s_in2   = (float2*)smraw;           // 4992 float2 (9984 floats)
    float2* s_conv2 = (float2*)smraw;           // ALIAS: 4096 float2, post-mainloop
    float*  s_wc    = smraw + 9984;             // 6400 floats [oc][icl][25]
    __shared__ float sred[16];

    const int n2 = blockIdx.x;
    const int tid = threadIdx.x;

    const float2* xin = g_h1p + n2 * 4608;
    for (int i = tid; i < 4608; i += 256) {
        int ic = i / 144;
        int r  = i - ic * 144;
        int rr = r / 12, c = r - rr * 12;
        s_in2[ic * 156 + rr * 13 + c] = xin[i];
    }

    const int oc = tid >> 2;
    const int q  = tid & 3;
    const int y0 = q * 2;

    u64 acc0[8], acc1[8];
    {
        float b = __ldg(bconv + oc);
        u64 bb = pack2(b, b);
#pragma unroll
        for (int i = 0; i < 8; i++) { acc0[i] = bb; acc1[i] = bb; }
    }

    for (int icb = 0; icb < 32; icb += 4) {
        __syncthreads();
        for (int j = tid; j < 6400; j += 256) {
            int o = j / 100, r = j - o * 100;
            s_wc[j] = w[(o * 32 + icb) * 25 + r];
        }
        __syncthreads();

        const float* wbase = s_wc + oc * 100;
#pragma unroll
        for (int icl = 0; icl < 4; icl++) {
            float wv[25];
#pragma unroll
            for (int i = 0; i < 25; i++) wv[i] = wbase[icl * 25 + i];
            const float2* ib = s_in2 + (icb + icl) * 156;
#pragma unroll
            for (int rr = 0; rr < 6; rr++) {
                u64 row[12];
                const u64* rp = (const u64*)(ib + (y0 + rr) * 13);
#pragma unroll
                for (int j = 0; j < 12; j++) row[j] = rp[j];
                if (rr < 5) {
#pragma unroll
                    for (int kw = 0; kw < 5; kw++) {
                        float s = wv[rr * 5 + kw];
                        u64 wd = pack2(s, s);
#pragma unroll
                        for (int ox = 0; ox < 8; ox++)
                            acc0[ox] = ffma2(wd, row[ox + kw], acc0[ox]);
                    }
                }
                if (rr >= 1) {
#pragma unroll
                    for (int kw = 0; kw < 5; kw++) {
                        float s = wv[(rr - 1) * 5 + kw];
                        u64 wd = pack2(s, s);
#pragma unroll
                        for (int ox = 0; ox < 8; ox++)
                            acc1[ox] = ffma2(wd, row[ox + kw], acc1[ox]);
                    }
                }
            }
        }
    }
    __syncthreads();   // all s_in2 reads done; safe to overwrite via alias

    float2 labs = make_float2(0.f, 0.f);
#pragma unroll
    for (int ox = 0; ox < 8; ox++) {
        float2 v0 = unpack2(acc0[ox]);
        float2 v1 = unpack2(acc1[ox]);
        s_conv2[oc * 64 + y0 * 8 + ox]       = v0;
        s_conv2[oc * 64 + (y0 + 1) * 8 + ox] = v1;
        labs.x += fabsf(v0.x) + fabsf(v1.x);
        labs.y += fabsf(v0.y) + fabsf(v1.y);
    }

    float2 tot = blockReduceSum2(labs, sred, tid);
    float d0 = 0.7f * tot.x / 4096.0f;
    float d1 = 0.7f * tot.y / 4096.0f;

    float2 ms = make_float2(0.f, 0.f), cn = make_float2(0.f, 0.f);
#pragma unroll
    for (int ox = 0; ox < 8; ox++) {
        float2 v0 = unpack2(acc0[ox]);
        float2 v1 = unpack2(acc1[ox]);
        float a;
        a = fabsf(v0.x); if (a > d0) { ms.x += a; cn.x += 1.f; }
        a = fabsf(v1.x); if (a > d0) { ms.x += a; cn.x += 1.f; }
        a = fabsf(v0.y); if (a > d1) { ms.y += a; cn.y += 1.f; }
        a = fabsf(v1.y); if (a > d1) { ms.y += a; cn.y += 1.f; }
    }
    ms = blockReduceSum2(ms, sred, tid);
    cn = blockReduceSum2(cn, sred, tid);
    float a0v = ms.x / cn.x;
    float a1v = ms.y / cn.y;

    float2* outp = g_h2p + n2 * 1024;
    for (int p = tid; p < 1024; p += 256) {
        int c = p >> 4;
        int r = p & 15;
        int py = r >> 2, px = r & 3;
        float sc = __ldg(bng + c) * BN_INV, sh = __ldg(bnb + c);
        const float2* base = s_conv2 + c * 64 + (py * 2) * 8 + px * 2;
        float m0 = -1e30f, m1 = -1e30f;
#pragma unroll
        for (int dy = 0; dy < 2; dy++)
#pragma unroll
            for (int dx = 0; dx < 2; dx++) {
                float2 v = base[dy * 8 + dx];
                float t0 = (v.x > d0) ? a0v : ((v.x < -d0) ? -a0v : 0.f);
                float t1 = (v.y > d1) ? a1v : ((v.y < -d1) ? -a1v : 0.f);
                m0 = fmaxf(m0, t0 * sc + sh);
                m1 = fmaxf(m1, t1 * sc + sh);
            }
        outp[p] = make_float2(fmaxf(m0, 0.f), fmaxf(m1, 0.f));
    }
}

// ---------------------------------------------------------------------------
// Kernel 3: fc1 + tern + relu + fc2 + tern -> out
// v5: 8 samples (4 pairs)/CTA, grid 256 -> 2 CTAs/SM (occ ~50%).
// 512 threads: 4 k-quarters x 128 oc-threads x 4 oc. acc = 16 u64 (32 regs).
// ---------------------------------------------------------------------------
#define SH 516

__global__ __launch_bounds__(512, 2) void k_fc(
    const float* __restrict__ b1, const float* __restrict__ w2,
    const float* __restrict__ b2, float* __restrict__ out) {
    extern __shared__ float sm[];
    float2* s_x2 = (float2*)sm;              // 4096 float2 (8192 floats)
    float*  s_hA = sm + 8192;                // 8*SH = 4128
    float*  s_hB = s_hA + 8 * SH;            // 4128
    float*  s_o  = s_hB + 8 * SH;            // 80
    float*  s_ad = s_o + 80;                 // 16

    const int tid = threadIdx.x;
    const int pr0 = blockIdx.x * 4;          // 4 sample pairs
    const int n0  = blockIdx.x * 8;          // 8 samples

    for (int i = tid; i < 4096; i += 512) s_x2[i] = g_h2p[pr0 * 1024 + i];
    __syncthreads();

    const int ocb = tid & 127;               // base oc
    const int qtr = tid >> 7;                // k-quarter 0..3
    const int kq0 = qtr * 64, kqe = kq0 + 64;

    u64 a[4][4];                             // [oc-j][pair]
#pragma unroll
    for (int j = 0; j < 4; j++) {
        u64 init = 0;
        if (qtr == 0) {
            float bv = b1[ocb + 128 * j];
            init = pack2(bv, bv);
        }
#pragma unroll
        for (int p = 0; p < 4; p++) a[j][p] = init;
    }

#pragma unroll 1
    for (int kq = kq0; kq < kqe; kq++) {
        const float* wb = g_w1q + kq * 2048;
        float4 w0 = *(const float4*)(wb + (ocb      ) * 4);
        float4 w1 = *(const float4*)(wb + (ocb + 128) * 4);
        float4 w2v = *(const float4*)(wb + (ocb + 256) * 4);
        float4 w3 = *(const float4*)(wb + (ocb + 384) * 4);
        const int kt = kq * 4;

        {   // substep A: k0, k1
            u64 W00 = pack2(w0.x, w0.x), W01 = pack2(w0.y, w0.y);
            u64 W10 = pack2(w1.x, w1.x), W11 = pack2(w1.y, w1.y);
            u64 W20 = pack2(w2v.x, w2v.x), W21 = pack2(w2v.y, w2v.y);
            u64 W30 = pack2(w3.x, w3.x), W31 = pack2(w3.y, w3.y);
#pragma unroll
            for (int p = 0; p < 4; p++) {
                ulonglong2 xa = *(const ulonglong2*)(s_x2 + p * 1024 + kt);
                a[0][p] = ffma2(W00, xa.x, a[0][p]);
                a[0][p] = ffma2(W01, xa.y, a[0][p]);
                a[1][p] = ffma2(W10, xa.x, a[1][p]);
                a[1][p] = ffma2(W11, xa.y, a[1][p]);
                a[2][p] = ffma2(W20, xa.x, a[2][p]);
                a[2][p] = ffma2(W21, xa.y, a[2][p]);
                a[3][p] = ffma2(W30, xa.x, a[3][p]);
                a[3][p] = ffma2(W31, xa.y, a[3][p]);
            }
        }
        {   // substep B: k2, k3
            u64 W00 = pack2(w0.z, w0.z), W01 = pack2(w0.w, w0.w);
            u64 W10 = pack2(w1.z, w1.z), W11 = pack2(w1.w, w1.w);
            u64 W20 = pack2(w2v.z, w2v.z), W21 = pack2(w2v.w, w2v.w);
            u64 W30 = pack2(w3.z, w3.z), W31 = pack2(w3.w, w3.w);
#pragma unroll
            for (int p = 0; p < 4; p++) {
                ulonglong2 xb = *(const ulonglong2*)(s_x2 + p * 1024 + kt + 2);
                a[0][p] = ffma2(W00, xb.x, a[0][p]);
                a[0][p] = ffma2(W01, xb.y, a[0][p]);
                a[1][p] = ffma2(W10, xb.x, a[1][p]);
                a[1][p] = ffma2(W11, xb.y, a[1][p]);
                a[2][p] = ffma2(W20, xb.x, a[2][p]);
                a[2][p] = ffma2(W21, xb.y, a[2][p]);
                a[3][p] = ffma2(W30, xb.x, a[3][p]);
                a[3][p] = ffma2(W31, xb.y, a[3][p]);
            }
        }
    }
    __syncthreads();

    // combine: q0 -> hA, q2 -> hB (write), then q1 -> hA, q3 -> hB (add)
    if (qtr == 0 || qtr == 2) {
        float* h = (qtr == 0) ? s_hA : s_hB;
#pragma unroll
        for (int j = 0; j < 4; j++) {
            int oc = ocb + 128 * j;
#pragma unroll
            for (int p = 0; p < 4; p++) {
                float2 v = unpack2(a[j][p]);
                h[(2 * p) * SH + oc]     = v.x;
                h[(2 * p + 1) * SH + oc] = v.y;
            }
        }
    }
    __syncthreads();
    if (qtr == 1 || qtr == 3) {
        float* h = (qtr == 1) ? s_hA : s_hB;
#pragma unroll
        for (int j = 0; j < 4; j++) {
            int oc = ocb + 128 * j;
#pragma unroll
            for (int p = 0; p < 4; p++) {
                float2 v = unpack2(a[j][p]);
                h[(2 * p) * SH + oc]     += v.x;
                h[(2 * p + 1) * SH + oc] += v.y;
            }
        }
    }
    __syncthreads();

    // per-sample ternarize params: warps 0..7 handle samples 0..7
    {
        int s = tid >> 5, j = tid & 31;
        if (s < 8) {
            float sum = 0.f;
            for (int i = j; i < 512; i += 32)
                sum += fabsf(s_hA[s * SH + i] + s_hB[s * SH + i]);
#pragma unroll
            for (int o = 16; o > 0; o >>= 1) sum += __shfl_xor_sync(0xffffffffu, sum, o);
            float d = 0.7f * sum / 512.0f;
            float msv = 0.f, c = 0.f;
            for (int i = j; i < 512; i += 32) {
                float a2 = fabsf(s_hA[s * SH + i] + s_hB[s * SH + i]);
                if (a2 > d) { msv += a2; c += 1.f; }
            }
#pragma unroll
            for (int o = 16; o > 0; o >>= 1) {
                msv += __shfl_xor_sync(0xffffffffu, msv, o);
                c   += __shfl_xor_sync(0xffffffffu, c, o);
            }
            if (j == 0) { s_ad[s] = d; s_ad[8 + s] = msv / c; }
        }
    }
    __syncthreads();

    // relu(ternarize(h)) -> s_hA (final)
    for (int i = tid; i < 4096; i += 512) {
        int s = i >> 9, k = i & 511;
        float v = s_hA[s * SH + k] + s_hB[s * SH + k];
        float d = s_ad[s], a2 = s_ad[8 + s];
        float t = (v > d) ? a2 : ((v < -d) ? -a2 : 0.f);
        s_hA[s * SH + k] = fmaxf(t, 0.f);
    }
    __syncthreads();

    // fc2: 8 samples x 10 outputs
    if (tid < 80) {
        int s = tid / 10, oc = tid - s * 10;
        float acc = b2[oc];
        const float* hp = s_hA + s * SH;
        const float* wp = w2 + oc * 512;
#pragma unroll 4
        for (int k = 0; k < 512; k += 4) {
            float4 wv4 = *(const float4*)(wp + k);
            float4 hv4 = *(const float4*)(hp + k);
            acc += hv4.x * wv4.x + hv4.y * wv4.y + hv4.z * wv4.z + hv4.w * wv4.w;
        }
        s_o[s * 10 + oc] = acc;
    }
    __syncthreads();

    if (tid < 8) {
        int s = tid;
        float v[10];
        float sum = 0.f;
#pragma unroll
        for (int j = 0; j < 10; j++) {
            v[j] = s_o[s * 10 + j];
            sum += fabsf(v[j]);
        }
        float d = 0.7f * sum / 10.0f;
        float msv = 0.f, c = 0.f;
#pragma unroll
        for (int j = 0; j < 10; j++) {
            float a2 = fabsf(v[j]);
            if (a2 > d) { msv += a2; c += 1.f; }
        }
        float a2 = msv / c;
        float* op = out + (n0 + s) * 10;
#pragma unroll
        for (int j = 0; j < 10; j++)
            op[j] = (v[j] > d) ? a2 : ((v[j] < -d) ? -a2 : 0.f);
    }
}

// ---------------------------------------------------------------------------
extern "C" void kernel_launch(void* const* d_in, const int* in_sizes, int n_in,
                              void* d_out, int out_size) {
    const float* x   = (const float*)d_in[0];
    const float* c1w = (const float*)d_in[1];
    const float* c1b = (const float*)d_in[2];
    const float* g1  = (const float*)d_in[3];
    const float* b1n = (const float*)d_in[4];
    const float* c2w = (const float*)d_in[5];
    const float* c2b = (const float*)d_in[6];
    const float* g2  = (const float*)d_in[7];
    const float* b2n = (const float*)d_in[8];
    const float* w1  = (const float*)d_in[9];
    const float* fb1 = (const float*)d_in[10];
    const float* w2  = (const float*)d_in[11];
    const float* fb2 = (const float*)d_in[12];
    float* out = (float*)d_out;

    const int B = in_sizes[0] / 784;

    const int smem1 = (2456 + 18464 * 2) * 4;          // 157,536 B
    const int smem2 = (9984 + 6400) * 4;               //  65,536 B
    const int smem3 = (8192 + 16 * SH + 96) * 4;       //  66,176 B -> 2 CTAs/SM
    cudaFuncSetAttribute(k_conv1, cudaFuncAttributeMaxDynamicSharedMemorySize, smem1);
    cudaFuncSetAttribute(k_conv2, cudaFuncAttributeMaxDynamicSharedMemorySize, smem2);
    cudaFuncSetAttribute(k_fc,    cudaFuncAttributeMaxDynamicSharedMemorySize, smem3);

    k_tw1<<<512, 256>>>(w1);
    k_conv1<<<B / 2, 256, smem1>>>(x, c1w, c1b, g1, b1n);
    k_conv2<<<B / 2, 256, smem2>>>(c2w, c2b, g2, b2n);
    k_fc<<<B / 8, 512, smem3>>>(fb1, w2, fb2, out);
}

// round 13
// speedup vs baseline: 1.0189x; 1.0189x over previous
#include <cuda_runtime.h>
#include <math.h>

#define BN_INV 0.9999950000374997f

typedef unsigned long long u64;

__device__ __forceinline__ u64 ffma2(u64 a, u64 b, u64 c) {
    u64 d;
    asm("fma.rn.f32x2 %0, %1, %2, %3;" : "=l"(d) : "l"(a), "l"(b), "l"(c));
    return d;
}
__device__ __forceinline__ u64 pack2(float lo, float hi) {
    u64 r;
    asm("mov.b64 %0, {%1, %2};" : "=l"(r) : "f"(lo), "f"(hi));
    return r;
}
__device__ __forceinline__ float2 unpack2(u64 v) {
    float2 f;
    asm("mov.b64 {%0, %1}, %2;" : "=f"(f.x), "=f"(f.y) : "l"(v));
    return f;
}

// Scratch (allocation-free rule -> __device__ globals)
__device__ float2 g_h1p[1024 * 4608];   // stage1 out, pair-interleaved
__device__ float2 g_h2p[1024 * 1024];   // stage2 out, pair-interleaved
__device__ float  g_w1q[1024 * 512];    // fc1 weights, [kq][oc][4] quad layout

// ---------------------------------------------------------------------------
// Paired block reduce, 256 threads (8 warps). sred >= 16 floats.
// ---------------------------------------------------------------------------
__device__ __forceinline__ float2 blockReduceSum2(float2 v, volatile float* sred, int tid) {
#pragma unroll
    for (int o = 16; o > 0; o >>= 1) {
        v.x += __shfl_xor_sync(0xffffffffu, v.x, o);
        v.y += __shfl_xor_sync(0xffffffffu, v.y, o);
    }
    if ((tid & 31) == 0) {
        sred[(tid >> 5) * 2]     = v.x;
        sred[(tid >> 5) * 2 + 1] = v.y;
    }
    __syncthreads();
    if (tid < 32) {
        float a = (tid < 8) ? sred[tid * 2] : 0.f;
        float b = (tid < 8) ? sred[tid * 2 + 1] : 0.f;
#pragma unroll
        for (int o = 4; o > 0; o >>= 1) {
            a += __shfl_xor_sync(0xffffffffu, a, o);
            b += __shfl_xor_sync(0xffffffffu, b, o);
        }
        if (tid == 0) { sred[0] = a; sred[1] = b; }
    }
    __syncthreads();
    float2 r = make_float2(sred[0], sred[1]);
    __syncthreads();
    return r;
}

// ---------------------------------------------------------------------------
// Paired block reduce, 384 threads (12 warps). sred >= 24 floats.
// ---------------------------------------------------------------------------
__device__ __forceinline__ float2 blockReduceSum2_384(float2 v, volatile float* sred, int tid) {
#pragma unroll
    for (int o = 16; o > 0; o >>= 1) {
        v.x += __shfl_xor_sync(0xffffffffu, v.x, o);
        v.y += __shfl_xor_sync(0xffffffffu, v.y, o);
    }
    if ((tid & 31) == 0) {
        sred[(tid >> 5) * 2]     = v.x;
        sred[(tid >> 5) * 2 + 1] = v.y;
    }
    __syncthreads();
    if (tid < 32) {
        float a = (tid < 12) ? sred[tid * 2] : 0.f;
        float b = (tid < 12) ? sred[tid * 2 + 1] : 0.f;
#pragma unroll
        for (int o = 8; o > 0; o >>= 1) {
            a += __shfl_xor_sync(0xffffffffu, a, o);
            b += __shfl_xor_sync(0xffffffffu, b, o);
        }
        if (tid == 0) { sred[0] = a; sred[1] = b; }
    }
    __syncthreads();
    float2 r = make_float2(sred[0], sred[1]);
    __syncthreads();
    return r;
}

// ---------------------------------------------------------------------------
// Kernel 0: repack fc1 weights  w1[512][1024] -> g_w1q[kq][oc][4]
// ---------------------------------------------------------------------------
__global__ __launch_bounds__(256) void k_tw1(const float* __restrict__ w1) {
    int idx = blockIdx.x * 256 + threadIdx.x;   // 131072 = 256 kq * 512 oc
    int kq = idx >> 9;
    int oc = idx & 511;
    float4 v = *(const float4*)(w1 + oc * 1024 + kq * 4);
    *(float4*)(g_w1q + kq * 2048 + oc * 4) = v;
}

// ---------------------------------------------------------------------------
// Kernel 1: conv1(1->32, 5x5, 28->24) + tern + BN + maxpool2 + relu
// v2: 384 threads (12 warps, 3/SMSP). Warp w -> rows w and w+12; lane = oc.
// Row LDS uniform broadcast; weights lane-stride 25 (conflict-free).
// ---------------------------------------------------------------------------
__global__ __launch_bounds__(384) void k_conv1(
    const float* __restrict__ x, const float* __restrict__ w,
    const float* __restrict__ bconv, const float* __restrict__ bng,
    const float* __restrict__ bnb) {
    extern __shared__ float sm[];
    float2* s_in2   = (float2*)sm;            // 812 float2
    float*  s_w     = sm + 1624;              // 800
    float*  s_b     = sm + 2424;              // 32
    float2* s_conv2 = (float2*)(sm + 2456);   // 32 * 577 = 18464 float2
    __shared__ float sred[32];

    const int n2 = blockIdx.x;
    const int tid = threadIdx.x;

    const float* x0 = x + (2 * n2) * 784;
    const float* x1 = x + (2 * n2 + 1) * 784;
    for (int i = tid; i < 784; i += 384) {
        int r = i / 28, c = i - r * 28;
        s_in2[r * 29 + c] = make_float2(x0[i], x1[i]);
    }
    for (int i = tid; i < 800; i += 384) s_w[i] = w[i];
    if (tid < 32) s_b[tid] = bconv[tid];
    __syncthreads();

    const int oc  = tid & 31;   // lane = output channel
    const int wrp = tid >> 5;   // warp id 0..11

    float2 labs = make_float2(0.f, 0.f);
#pragma unroll
    for (int p = 0; p < 2; p++) {
        int oy = p * 12 + wrp;  // rows wrp and wrp+12
        u64 acc[24];
        {
            float b = s_b[oc];
            u64 bb = pack2(b, b);
#pragma unroll
            for (int ox = 0; ox < 24; ox++) acc[ox] = bb;
        }
#pragma unroll
        for (int kh = 0; kh < 5; kh++) {
            u64 row[28];                                    // uniform per warp -> broadcast
            const u64* rp = (const u64*)(s_in2 + (oy + kh) * 29);
#pragma unroll
            for (int j = 0; j < 28; j++) row[j] = rp[j];
            const float* wp = s_w + oc * 25 + kh * 5;       // lane stride 25: conflict-free
#pragma unroll
            for (int kw = 0; kw < 5; kw++) {
                float s = wp[kw];
                u64 wd = pack2(s, s);
#pragma unroll
                for (int ox = 0; ox < 24; ox++)
                    acc[ox] = ffma2(wd, row[ox + kw], acc[ox]);
            }
        }
        float2* cp = s_conv2 + oc * 577 + oy * 24;
#pragma unroll
        for (int ox = 0; ox < 24; ox++) {
            float2 v = unpack2(acc[ox]);
            cp[ox] = v;
            labs.x += fabsf(v.x);
            labs.y += fabsf(v.y);
        }
    }

    float2 tot = blockReduceSum2_384(labs, sred, tid);
    float d0 = 0.7f * tot.x / 18432.0f;
    float d1 = 0.7f * tot.y / 18432.0f;

    float2 ms = make_float2(0.f, 0.f), cn = make_float2(0.f, 0.f);
    for (int i = tid; i < 18432; i += 384) {
        int c = i / 576, r = i - c * 576;
        float2 v = s_conv2[c * 577 + r];
        float a;
        a = fabsf(v.x); if (a > d0) { ms.x += a; cn.x += 1.f; }
        a = fabsf(v.y); if (a > d1) { ms.y += a; cn.y += 1.f; }
    }
    ms = blockReduceSum2_384(ms, sred, tid);
    cn = blockReduceSum2_384(cn, sred, tid);
    float a0v = ms.x / cn.x;
    float a1v = ms.y / cn.y;

    float2* outp = g_h1p + n2 * 4608;
    for (int p = tid; p < 4608; p += 384) {
        int c = p / 144;
        int r = p - c * 144;
        int py = r / 12, px = r - py * 12;
        float sc = __ldg(bng + c) * BN_INV, sh = __ldg(bnb + c);
        const float2* base = s_conv2 + c * 577 + (py * 2) * 24 + px * 2;
        float m0 = -1e30f, m1 = -1e30f;
#pragma unroll
        for (int dy = 0; dy < 2; dy++)
#pragma unroll
            for (int dx = 0; dx < 2; dx++) {
                float2 v = base[dy * 24 + dx];
                float t0 = (v.x > d0) ? a0v : ((v.x < -d0) ? -a0v : 0.f);
                float t1 = (v.y > d1) ? a1v : ((v.y < -d1) ? -a1v : 0.f);
                m0 = fmaxf(m0, t0 * sc + sh);
                m1 = fmaxf(m1, t1 * sc + sh);
            }
        outp[p] = make_float2(fmaxf(m0, 0.f), fmaxf(m1, 0.f));
    }
}

// ---------------------------------------------------------------------------
// Kernel 2: conv2(32->64, 5x5, 12->8) + tern + BN + maxpool2 + relu
// 2 samples/CTA f32x2, staged weights, s_conv2 aliases s_in2. (unchanged)
// ---------------------------------------------------------------------------
__global__ __launch_bounds__(256) void k_conv2(
    const float* __restrict__ w, const float* __restrict__ bconv,
    const float* __restrict__ bng, const float* __restrict__ bnb) {
    extern __shared__ float smraw[];
    float2* s_in2   = (float2*)smraw;           // 4992 float2 (9984 floats)
    float2* s_conv2 = (float2*)smraw;           // ALIAS: 4096 float2, post-mainloop
    float*  s_wc    = smraw + 9984;             // 6400 floats [oc][icl][25]
    __shared__ float sred[16];

    const int n2 = blockIdx.x;
    const int tid = threadIdx.x;

    const float2* xin = g_h1p + n2 * 4608;
    for (int i = tid; i < 4608; i += 256) {
        int ic = i / 144;
        int r  = i - ic * 144;
        int rr = r / 12, c = r - rr * 12;
        s_in2[ic * 156 + rr * 13 + c] = xin[i];
    }

    const int oc = tid >> 2;
    const int q  = tid & 3;
    const int y0 = q * 2;

    u64 acc0[8], acc1[8];
    {
        float b = __ldg(bconv + oc);
        u64 bb = pack2(b, b);
#pragma unroll
        for (int i = 0; i < 8; i++) { acc0[i] = bb; acc1[i] = bb; }
    }

    for (int icb = 0; icb < 32; icb += 4) {
        __syncthreads();
        for (int j = tid; j < 6400; j += 256) {
            int o = j / 100, r = j - o * 100;
            s_wc[j] = w[(o * 32 + icb) * 25 + r];
        }
        __syncthreads();

        const float* wbase = s_wc + oc * 100;
#pragma unroll
        for (int icl = 0; icl < 4; icl++) {
            float wv[25];
#pragma unroll
            for (int i = 0; i < 25; i++) wv[i] = wbase[icl * 25 + i];
            const float2* ib = s_in2 + (icb + icl) * 156;
#pragma unroll
            for (int rr = 0; rr < 6; rr++) {
                u64 row[12];
                const u64* rp = (const u64*)(ib + (y0 + rr) * 13);
#pragma unroll
                for (int j = 0; j < 12; j++) row[j] = rp[j];
                if (rr < 5) {
#pragma unroll
                    for (int kw = 0; kw < 5; kw++) {
                        float s = wv[rr * 5 + kw];
                        u64 wd = pack2(s, s);
#pragma unroll
                        for (int ox = 0; ox < 8; ox++)
                            acc0[ox] = ffma2(wd, row[ox + kw], acc0[ox]);
                    }
                }
                if (rr >= 1) {
#pragma unroll
                    for (int kw = 0; kw < 5; kw++) {
                        float s = wv[(rr - 1) * 5 + kw];
                        u64 wd = pack2(s, s);
#pragma unroll
                        for (int ox = 0; ox < 8; ox++)
                            acc1[ox] = ffma2(wd, row[ox + kw], acc1[ox]);
                    }
                }
            }
        }
    }
    __syncthreads();   // all s_in2 reads done; safe to overwrite via alias

    float2 labs = make_float2(0.f, 0.f);
#pragma unroll
    for (int ox = 0; ox < 8; ox++) {
        float2 v0 = unpack2(acc0[ox]);
        float2 v1 = unpack2(acc1[ox]);
        s_conv2[oc * 64 + y0 * 8 + ox]       = v0;
        s_conv2[oc * 64 + (y0 + 1) * 8 + ox] = v1;
        labs.x += fabsf(v0.x) + fabsf(v1.x);
        labs.y += fabsf(v0.y) + fabsf(v1.y);
    }

    float2 tot = blockReduceSum2(labs, sred, tid);
    float d0 = 0.7f * tot.x / 4096.0f;
    float d1 = 0.7f * tot.y / 4096.0f;

    float2 ms = make_float2(0.f, 0.f), cn = make_float2(0.f, 0.f);
#pragma unroll
    for (int ox = 0; ox < 8; ox++) {
        float2 v0 = unpack2(acc0[ox]);
        float2 v1 = unpack2(acc1[ox]);
        float a;
        a = fabsf(v0.x); if (a > d0) { ms.x += a; cn.x += 1.f; }
        a = fabsf(v1.x); if (a > d0) { ms.x += a; cn.x += 1.f; }
        a = fabsf(v0.y); if (a > d1) { ms.y += a; cn.y += 1.f; }
        a = fabsf(v1.y); if (a > d1) { ms.y += a; cn.y += 1.f; }
    }
    ms = blockReduceSum2(ms, sred, tid);
    cn = blockReduceSum2(cn, sred, tid);
    float a0v = ms.x / cn.x;
    float a1v = ms.y / cn.y;

    float2* outp = g_h2p + n2 * 1024;
    for (int p = tid; p < 1024; p += 256) {
        int c = p >> 4;
        int r = p & 15;
        int py = r >> 2, px = r & 3;
        float sc = __ldg(bng + c) * BN_INV, sh = __ldg(bnb + c);
        const float2* base = s_conv2 + c * 64 + (py * 2) * 8 + px * 2;
        float m0 = -1e30f, m1 = -1e30f;
#pragma unroll
        for (int dy = 0; dy < 2; dy++)
#pragma unroll
            for (int dx = 0; dx < 2; dx++) {
                float2 v = base[dy * 8 + dx];
                float t0 = (v.x > d0) ? a0v : ((v.x < -d0) ? -a0v : 0.f);
                float t1 = (v.y > d1) ? a1v : ((v.y < -d1) ? -a1v : 0.f);
                m0 = fmaxf(m0, t0 * sc + sh);
                m1 = fmaxf(m1, t1 * sc + sh);
            }
        outp[p] = make_float2(fmaxf(m0, 0.f), fmaxf(m1, 0.f));
    }
}

// ---------------------------------------------------------------------------
// Kernel 3: fc1 + tern + relu + fc2 + tern -> out
// v5: 8 samples (4 pairs)/CTA, grid 256, 2 CTAs/SM. (unchanged)
// ---------------------------------------------------------------------------
#define SH 516

__global__ __launch_bounds__(512, 2) void k_fc(
    const float* __restrict__ b1, const float* __restrict__ w2,
    const float* __restrict__ b2, float* __restrict__ out) {
    extern __shared__ float sm[];
    float2* s_x2 = (float2*)sm;              // 4096 float2 (8192 floats)
    float*  s_hA = sm + 8192;                // 8*SH = 4128
    float*  s_hB = s_hA + 8 * SH;            // 4128
    float*  s_o  = s_hB + 8 * SH;            // 80
    float*  s_ad = s_o + 80;                 // 16

    const int tid = threadIdx.x;
    const int pr0 = blockIdx.x * 4;          // 4 sample pairs
    const int n0  = blockIdx.x * 8;          // 8 samples

    for (int i = tid; i < 4096; i += 512) s_x2[i] = g_h2p[pr0 * 1024 + i];
    __syncthreads();

    const int ocb = tid & 127;               // base oc
    const int qtr = tid >> 7;                // k-quarter 0..3
    const int kq0 = qtr * 64, kqe = kq0 + 64;

    u64 a[4][4];                             // [oc-j][pair]
#pragma unroll
    for (int j = 0; j < 4; j++) {
        u64 init = 0;
        if (qtr == 0) {
            float bv = b1[ocb + 128 * j];
            init = pack2(bv, bv);
        }
#pragma unroll
        for (int p = 0; p < 4; p++) a[j][p] = init;
    }

#pragma unroll 1
    for (int kq = kq0; kq < kqe; kq++) {
        const float* wb = g_w1q + kq * 2048;
        float4 w0 = *(const float4*)(wb + (ocb      ) * 4);
        float4 w1 = *(const float4*)(wb + (ocb + 128) * 4);
        float4 w2v = *(const float4*)(wb + (ocb + 256) * 4);
        float4 w3 = *(const float4*)(wb + (ocb + 384) * 4);
        const int kt = kq * 4;

        {   // substep A: k0, k1
            u64 W00 = pack2(w0.x, w0.x), W01 = pack2(w0.y, w0.y);
            u64 W10 = pack2(w1.x, w1.x), W11 = pack2(w1.y, w1.y);
            u64 W20 = pack2(w2v.x, w2v.x), W21 = pack2(w2v.y, w2v.y);
            u64 W30 = pack2(w3.x, w3.x), W31 = pack2(w3.y, w3.y);
#pragma unroll
            for (int p = 0; p < 4; p++) {
                ulonglong2 xa = *(const ulonglong2*)(s_x2 + p * 1024 + kt);
                a[0][p] = ffma2(W00, xa.x, a[0][p]);
                a[0][p] = ffma2(W01, xa.y, a[0][p]);
                a[1][p] = ffma2(W10, xa.x, a[1][p]);
                a[1][p] = ffma2(W11, xa.y, a[1][p]);
                a[2][p] = ffma2(W20, xa.x, a[2][p]);
                a[2][p] = ffma2(W21, xa.y, a[2][p]);
                a[3][p] = ffma2(W30, xa.x, a[3][p]);
                a[3][p] = ffma2(W31, xa.y, a[3][p]);
            }
        }
        {   // substep B: k2, k3
            u64 W00 = pack2(w0.z, w0.z), W01 = pack2(w0.w, w0.w);
            u64 W10 = pack2(w1.z, w1.z), W11 = pack2(w1.w, w1.w);
            u64 W20 = pack2(w2v.z, w2v.z), W21 = pack2(w2v.w, w2v.w);
            u64 W30 = pack2(w3.z, w3.z), W31 = pack2(w3.w, w3.w);
#pragma unroll
            for (int p = 0; p < 4; p++) {
                ulonglong2 xb = *(const ulonglong2*)(s_x2 + p * 1024 + kt + 2);
                a[0][p] = ffma2(W00, xb.x, a[0][p]);
                a[0][p] = ffma2(W01, xb.y, a[0][p]);
                a[1][p] = ffma2(W10, xb.x, a[1][p]);
                a[1][p] = ffma2(W11, xb.y, a[1][p]);
                a[2][p] = ffma2(W20, xb.x, a[2][p]);
                a[2][p] = ffma2(W21, xb.y, a[2][p]);
                a[3][p] = ffma2(W30, xb.x, a[3][p]);
                a[3][p] = ffma2(W31, xb.y, a[3][p]);
            }
        }
    }
    __syncthreads();

    // combine: q0 -> hA, q2 -> hB (write), then q1 -> hA, q3 -> hB (add)
    if (qtr == 0 || qtr == 2) {
        float* h = (qtr == 0) ? s_hA : s_hB;
#pragma unroll
        for (int j = 0; j < 4; j++) {
            int oc = ocb + 128 * j;
#pragma unroll
            for (int p = 0; p < 4; p++) {
                float2 v = unpack2(a[j][p]);
                h[(2 * p) * SH + oc]     = v.x;
                h[(2 * p + 1) * SH + oc] = v.y;
            }
        }
    }
    __syncthreads();
    if (qtr == 1 || qtr == 3) {
        float* h = (qtr == 1) ? s_hA : s_hB;
#pragma unroll
        for (int j = 0; j < 4; j++) {
            int oc = ocb + 128 * j;
#pragma unroll
            for (int p = 0; p < 4; p++) {
                float2 v = unpack2(a[j][p]);
                h[(2 * p) * SH + oc]     += v.x;
                h[(2 * p + 1) * SH + oc] += v.y;
            }
        }
    }
    __syncthreads();

    // per-sample ternarize params: warps 0..7 handle samples 0..7
    {
        int s = tid >> 5, j = tid & 31;
        if (s < 8) {
            float sum = 0.f;
            for (int i = j; i < 512; i += 32)
                sum += fabsf(s_hA[s * SH + i] + s_hB[s * SH + i]);
#pragma unroll
            for (int o = 16; o > 0; o >>= 1) sum += __shfl_xor_sync(0xffffffffu, sum, o);
            float d = 0.7f * sum / 512.0f;
            float msv = 0.f, c = 0.f;
            for (int i = j; i < 512; i += 32) {
                float a2 = fabsf(s_hA[s * SH + i] + s_hB[s * SH + i]);
                if (a2 > d) { msv += a2; c += 1.f; }
            }
#pragma unroll
            for (int o = 16; o > 0; o >>= 1) {
                msv += __shfl_xor_sync(0xffffffffu, msv, o);
                c   += __shfl_xor_sync(0xffffffffu, c, o);
            }
            if (j == 0) { s_ad[s] = d; s_ad[8 + s] = msv / c; }
        }
    }
    __syncthreads();

    // relu(ternarize(h)) -> s_hA (final)
    for (int i = tid; i < 4096; i += 512) {
        int s = i >> 9, k = i & 511;
        float v = s_hA[s * SH + k] + s_hB[s * SH + k];
        float d = s_ad[s], a2 = s_ad[8 + s];
        float t = (v > d) ? a2 : ((v < -d) ? -a2 : 0.f);
        s_hA[s * SH + k] = fmaxf(t, 0.f);
    }
    __syncthreads();

    // fc2: 8 samples x 10 outputs
    if (tid < 80) {
        int s = tid / 10, oc = tid - s * 10;
        float acc = b2[oc];
        const float* hp = s_hA + s * SH;
        const float* wp = w2 + oc * 512;
#pragma unroll 4
        for (int k = 0; k < 512; k += 4) {
            float4 wv4 = *(const float4*)(wp + k);
            float4 hv4 = *(const float4*)(hp + k);
            acc += hv4.x * wv4.x + hv4.y * wv4.y + hv4.z * wv4.z + hv4.w * wv4.w;
        }
        s_o[s * 10 + oc] = acc;
    }
    __syncthreads();

    if (tid < 8) {
        int s = tid;
        float v[10];
        float sum = 0.f;
#pragma unroll
        for (int j = 0; j < 10; j++) {
            v[j] = s_o[s * 10 + j];
            sum += fabsf(v[j]);
        }
        float d = 0.7f * sum / 10.0f;
        float msv = 0.f, c = 0.f;
#pragma unroll
        for (int j = 0; j < 10; j++) {
            float a2 = fabsf(v[j]);
            if (a2 > d) { msv += a2; c += 1.f; }
        }
        float a2 = msv / c;
        float* op = out + (n0 + s) * 10;
#pragma unroll
        for (int j = 0; j < 10; j++)
            op[j] = (v[j] > d) ? a2 : ((v[j] < -d) ? -a2 : 0.f);
    }
}

// ---------------------------------------------------------------------------
extern "C" void kernel_launch(void* const* d_in, const int* in_sizes, int n_in,
                              void* d_out, int out_size) {
    const float* x   = (const float*)d_in[0];
    const float* c1w = (const float*)d_in[1];
    const float* c1b = (const float*)d_in[2];
    const float* g1  = (const float*)d_in[3];
    const float* b1n = (const float*)d_in[4];
    const float* c2w = (const float*)d_in[5];
    const float* c2b = (const float*)d_in[6];
    const float* g2  = (const float*)d_in[7];
    const float* b2n = (const float*)d_in[8];
    const float* w1  = (const float*)d_in[9];
    const float* fb1 = (const float*)d_in[10];
    const float* w2  = (const float*)d_in[11];
    const float* fb2 = (const float*)d_in[12];
    float* out = (float*)d_out;

    const int B = in_sizes[0] / 784;

    const int smem1 = (2456 + 18464 * 2) * 4;          // 157,536 B
    const int smem2 = (9984 + 6400) * 4;               //  65,536 B
    const int smem3 = (8192 + 16 * SH + 96) * 4;       //  66,176 B -> 2 CTAs/SM
    cudaFuncSetAttribute(k_conv1, cudaFuncAttributeMaxDynamicSharedMemorySize, smem1);
    cudaFuncSetAttribute(k_conv2, cudaFuncAttributeMaxDynamicSharedMemorySize, smem2);
    cudaFuncSetAttribute(k_fc,    cudaFuncAttributeMaxDynamicSharedMemorySize, smem3);

    k_tw1<<<512, 256>>>(w1);
    k_conv1<<<B / 2, 384, smem1>>>(x, c1w, c1b, g1, b1n);
    k_conv2<<<B / 2, 256, smem2>>>(c2w, c2b, g2, b2n);
    k_fc<<<B / 8, 512, smem3>>>(fb1, w2, fb2, out);
}